// round 9
// baseline (speedup 1.0000x reference)
#include <cuda_runtime.h>
#include <cuda_bf16.h>

// VectorQuantizer B=32,C=64,H=64,W=64,K=512 — mma.sync bf16 3-term split (base sm_103)
// out layout: [0,8388608) ste-out | [+0] loss | [+1] unique | [+2,+32770) new_codebook

#define C_ 64
#define HW_ 4096
#define CHW_ 262144
#define K_ 512
#define NTILES 1024
#define GRID_ 148
#define THREADS_ 256
#define OUT_ELEMS 8388608
#define TAU 0.004f

typedef unsigned int u32;

__device__ float g_counts[K_];
__device__ float g_sums[K_ * C_];
__device__ float g_commit;

// ---- smem layout (bytes) ----
#define OFF_BHI  0        // codebook hi bf16 [512][64], swizzled rows of 128B (64KB)
#define OFF_BLO  65536    // lo (64KB)
#define OFF_AHI  131072   // x hi bf16 [128][64] swizzled (16KB)
#define OFF_ALO  147456   // lo (16KB)
#define OFF_XF   163840   // x fp32, channel-major [64][128] (32KB)
#define OFF_NEGE 196608   // f32[512] = -0.5*|e|^2
#define OFF_ESQ  198656   // f32[512] = |e|^2
#define OFF_CNT  200704   // f32[512] histogram
#define OFF_B1S  202752   // f32[2][128]
#define OFF_B2S  203776   // f32[2][128]
#define OFF_K1S  204800   // int[2][128]
#define OFF_KARR 205824   // int[128]
#define OFF_QR   206336   // int[128] repair queue
#define OFF_QC   206848   // int
#define OFF_RED  206852   // f32[8]
#define SMEM_TOTAL 206912

__device__ __forceinline__ u32 pk2(__nv_bfloat16 a, __nv_bfloat16 b) {
    return (u32)__bfloat16_as_ushort(a) | ((u32)__bfloat16_as_ushort(b) << 16);
}
// row-swizzled address: 128B rows, XOR bits[6:4] with row%8 (conflict-free frag loads)
__device__ __forceinline__ int swz(int r, int cbyte) {
    return r * 128 + (cbyte ^ ((r & 7) << 4));
}

#define MMA(c, a0, a1, a2, a3, b0, b1)                                        \
    asm volatile("mma.sync.aligned.m16n8k16.row.col.f32.bf16.bf16.f32 "       \
                 "{%0,%1,%2,%3}, {%4,%5,%6,%7}, {%8,%9}, {%0,%1,%2,%3};"      \
                 : "+f"((c)[0]), "+f"((c)[1]), "+f"((c)[2]), "+f"((c)[3])     \
                 : "r"(a0), "r"(a1), "r"(a2), "r"(a3), "r"(b0), "r"(b1))

__global__ void vq_nop() {}

// ================= main =================
__global__ void __launch_bounds__(THREADS_, 1) vq_main(
    const float* __restrict__ x, const float* __restrict__ cb,
    float* __restrict__ out)
{
    extern __shared__ char sm[];
    float* nege = (float*)(sm + OFF_NEGE);
    float* esq  = (float*)(sm + OFF_ESQ);
    float* scnt = (float*)(sm + OFF_CNT);
    float* b1s  = (float*)(sm + OFF_B1S);
    float* b2s  = (float*)(sm + OFF_B2S);
    int*   k1s  = (int*)(sm + OFF_K1S);
    int*   karr = (int*)(sm + OFF_KARR);
    int*   qrw  = (int*)(sm + OFF_QR);
    int*   qc   = (int*)(sm + OFF_QC);
    float* sred = (float*)(sm + OFF_RED);
    float* xf   = (float*)(sm + OFF_XF);

    const int tid = threadIdx.x;
    const int wid = tid >> 5, l = tid & 31;
    const int wRow = wid >> 1, wCol = wid & 1;   // warp grid 4x2 over (rows, codes)
    const int lq = l >> 2, lr = l & 3;           // frag row / col index within quad

    // ---- prologue: codebook -> bf16 hi/lo swizzled smem; |e|^2; zero hist ----
    const float4* cb4 = (const float4*)cb;
    for (int i = tid; i < K_ * 16; i += THREADS_) {
        float4 f = cb4[i];
        int code = i >> 4, j = i & 15;           // channels 4j..4j+3
        __nv_bfloat16 h0 = __float2bfloat16(f.x), h1 = __float2bfloat16(f.y);
        __nv_bfloat16 h2 = __float2bfloat16(f.z), h3 = __float2bfloat16(f.w);
        __nv_bfloat16 l0 = __float2bfloat16(f.x - __bfloat162float(h0));
        __nv_bfloat16 l1 = __float2bfloat16(f.y - __bfloat162float(h1));
        __nv_bfloat16 l2 = __float2bfloat16(f.z - __bfloat162float(h2));
        __nv_bfloat16 l3 = __float2bfloat16(f.w - __bfloat162float(h3));
        int a = swz(code, 8 * j);
        *(u32*)(sm + OFF_BHI + a)     = pk2(h0, h1);
        *(u32*)(sm + OFF_BHI + a + 4) = pk2(h2, h3);
        *(u32*)(sm + OFF_BLO + a)     = pk2(l0, l1);
        *(u32*)(sm + OFF_BLO + a + 4) = pk2(l2, l3);
    }
#pragma unroll
    for (int r = 0; r < 2; r++) {
        int k = tid * 2 + r;
        const float* e = cb + k * C_;
        float s = 0.f;
#pragma unroll
        for (int c = 0; c < C_; c++) s = fmaf(e[c], e[c], s);
        esq[k] = s;
        nege[k] = -0.5f * s;
        scnt[k] = 0.f;
    }
    __syncthreads();

    float csum = 0.f;

    for (int tile = blockIdx.x; tile < NTILES; tile += GRID_) {
        const int nb = tile >> 5;               // batch index (128-row tiles, 32/batch)
        const int hwb = (tile & 31) * 128;      // hw base
        const float* xb = x + (size_t)nb * CHW_ + hwb;

        if (tid == 0) *qc = 0;
        // ---- load 128 x-rows: fp32 (channel-major) + bf16 hi/lo swizzled ----
#pragma unroll
        for (int it = 0; it < 16; it++) {
            int i = it * 256 + tid;
            int cp = i >> 7, r = i & 127;       // channel pair, row
            float f0 = xb[(2 * cp) * HW_ + r];
            float f1 = xb[(2 * cp + 1) * HW_ + r];
            __nv_bfloat16 h0 = __float2bfloat16(f0), h1 = __float2bfloat16(f1);
            __nv_bfloat16 q0 = __float2bfloat16(f0 - __bfloat162float(h0));
            __nv_bfloat16 q1 = __float2bfloat16(f1 - __bfloat162float(h1));
            int a = swz(r, 4 * cp);
            *(u32*)(sm + OFF_AHI + a) = pk2(h0, h1);
            *(u32*)(sm + OFF_ALO + a) = pk2(q0, q1);
            xf[(2 * cp) * 128 + r]     = f0;
            xf[(2 * cp + 1) * 128 + r] = f1;
        }
        __syncthreads();

        // ---- A fragments for this warp's 32 rows (2 strips of 16) ----
        u32 Ah[2][4][4], Al[2][4][4];
#pragma unroll
        for (int s = 0; s < 2; s++)
#pragma unroll
            for (int ks = 0; ks < 4; ks++) {
                int r0 = wRow * 32 + s * 16 + lq, r1 = r0 + 8;
                int cb0 = 32 * ks + 4 * lr;
                Ah[s][ks][0] = *(u32*)(sm + OFF_AHI + swz(r0, cb0));
                Ah[s][ks][1] = *(u32*)(sm + OFF_AHI + swz(r1, cb0));
                Ah[s][ks][2] = *(u32*)(sm + OFF_AHI + swz(r0, cb0 + 16));
                Ah[s][ks][3] = *(u32*)(sm + OFF_AHI + swz(r1, cb0 + 16));
                Al[s][ks][0] = *(u32*)(sm + OFF_ALO + swz(r0, cb0));
                Al[s][ks][1] = *(u32*)(sm + OFF_ALO + swz(r1, cb0));
                Al[s][ks][2] = *(u32*)(sm + OFF_ALO + swz(r0, cb0 + 16));
                Al[s][ks][3] = *(u32*)(sm + OFF_ALO + swz(r1, cb0 + 16));
            }

        float b1v[4], b2v[4];
        int k1v[4];
#pragma unroll
        for (int rs = 0; rs < 4; rs++) { b1v[rs] = -3.402823466e38f; b2v[rs] = -3.402823466e38f; k1v[rs] = 0; }

        // ---- main: 32 chunks of 8 codes; 24 HMMA per chunk ----
#pragma unroll 1
        for (int ch = 0; ch < 32; ch++) {
            int colb = wCol * 256 + ch * 8;
            int n = colb + lq;                  // code row for B frag
            float C0[4] = {0.f, 0.f, 0.f, 0.f}, C1[4] = {0.f, 0.f, 0.f, 0.f};
#pragma unroll
            for (int ks = 0; ks < 4; ks++) {
                int cbB = 32 * ks + 4 * lr;
                u32 bh0 = *(u32*)(sm + OFF_BHI + swz(n, cbB));
                u32 bh1 = *(u32*)(sm + OFF_BHI + swz(n, cbB + 16));
                u32 bl0 = *(u32*)(sm + OFF_BLO + swz(n, cbB));
                u32 bl1 = *(u32*)(sm + OFF_BLO + swz(n, cbB + 16));
                MMA(C0, Ah[0][ks][0], Ah[0][ks][1], Ah[0][ks][2], Ah[0][ks][3], bh0, bh1);
                MMA(C1, Ah[1][ks][0], Ah[1][ks][1], Ah[1][ks][2], Ah[1][ks][3], bh0, bh1);
                MMA(C0, Ah[0][ks][0], Ah[0][ks][1], Ah[0][ks][2], Ah[0][ks][3], bl0, bl1);
                MMA(C1, Ah[1][ks][0], Ah[1][ks][1], Ah[1][ks][2], Ah[1][ks][3], bl0, bl1);
                MMA(C0, Al[0][ks][0], Al[0][ks][1], Al[0][ks][2], Al[0][ks][3], bh0, bh1);
                MMA(C1, Al[1][ks][0], Al[1][ks][1], Al[1][ks][2], Al[1][ks][3], bh0, bh1);
            }
            int col0 = colb + 2 * lr;
            float ng0 = nege[col0], ng1 = nege[col0 + 1];
            float t;
            // strip0: rowslots 0 (row lq), 1 (row lq+8); strip1: rowslots 2,3
            t = C0[0] + ng0; if (t > b1v[0]) { b2v[0] = b1v[0]; b1v[0] = t; k1v[0] = col0; }     else b2v[0] = fmaxf(b2v[0], t);
            t = C0[1] + ng1; if (t > b1v[0]) { b2v[0] = b1v[0]; b1v[0] = t; k1v[0] = col0 + 1; } else b2v[0] = fmaxf(b2v[0], t);
            t = C0[2] + ng0; if (t > b1v[1]) { b2v[1] = b1v[1]; b1v[1] = t; k1v[1] = col0; }     else b2v[1] = fmaxf(b2v[1], t);
            t = C0[3] + ng1; if (t > b1v[1]) { b2v[1] = b1v[1]; b1v[1] = t; k1v[1] = col0 + 1; } else b2v[1] = fmaxf(b2v[1], t);
            t = C1[0] + ng0; if (t > b1v[2]) { b2v[2] = b1v[2]; b1v[2] = t; k1v[2] = col0; }     else b2v[2] = fmaxf(b2v[2], t);
            t = C1[1] + ng1; if (t > b1v[2]) { b2v[2] = b1v[2]; b1v[2] = t; k1v[2] = col0 + 1; } else b2v[2] = fmaxf(b2v[2], t);
            t = C1[2] + ng0; if (t > b1v[3]) { b2v[3] = b1v[3]; b1v[3] = t; k1v[3] = col0; }     else b2v[3] = fmaxf(b2v[3], t);
            t = C1[3] + ng1; if (t > b1v[3]) { b2v[3] = b1v[3]; b1v[3] = t; k1v[3] = col0 + 1; } else b2v[3] = fmaxf(b2v[3], t);
        }

        // ---- merge top-2 across the quad (4 lanes share each row) ----
#pragma unroll
        for (int off = 1; off <= 2; off <<= 1) {
#pragma unroll
            for (int rs = 0; rs < 4; rs++) {
                float ob1 = __shfl_xor_sync(0xffffffffu, b1v[rs], off);
                float ob2 = __shfl_xor_sync(0xffffffffu, b2v[rs], off);
                int   ok  = __shfl_xor_sync(0xffffffffu, k1v[rs], off);
                float nb2 = fmaxf(fmaxf(b2v[rs], ob2), fminf(b1v[rs], ob1));
                if (ob1 > b1v[rs] || (ob1 == b1v[rs] && ok < k1v[rs])) { b1v[rs] = ob1; k1v[rs] = ok; }
                b2v[rs] = nb2;
            }
        }
        if (lr == 0) {
#pragma unroll
            for (int rs = 0; rs < 4; rs++) {
                int row = wRow * 32 + (rs >> 1) * 16 + (rs & 1) * 8 + lq;
                b1s[wCol * 128 + row] = b1v[rs];
                b2s[wCol * 128 + row] = b2v[rs];
                k1s[wCol * 128 + row] = k1v[rs];
            }
        }
        __syncthreads();

        // ---- merge code-halves, detect near-ties ----
        if (tid < 128) {
            float A1 = b1s[tid], A2 = b2s[tid]; int Ak = k1s[tid];
            float B1 = b1s[128 + tid], B2 = b2s[128 + tid]; int Bk = k1s[128 + tid];
            float m2 = fmaxf(fmaxf(A2, B2), fminf(A1, B1));
            float m1; int kk;
            if (B1 > A1 || (B1 == A1 && Bk < Ak)) { m1 = B1; kk = Bk; } else { m1 = A1; kk = Ak; }
            karr[tid] = kk;
            if (m1 - m2 < TAU) { int qi = atomicAdd(qc, 1); qrw[qi] = tid; }
        }
        __syncthreads();

        // ---- exact fp32 repair: full 512-code rescan, 16 lanes per row ----
        {
            int nq = *qc;
            int g = tid >> 4, l16 = tid & 15;
            u32 gmask = 0xFFFFu << (tid & 16);
            for (int qi = g; qi < nq; qi += 16) {
                int r = qrw[qi];
                float xv[C_];
#pragma unroll
                for (int c = 0; c < C_; c++) xv[c] = xf[c * 128 + r];
                float db = 3.402823466e38f; int kb = 0;
                for (int k2 = l16 * 32; k2 < l16 * 32 + 32; k2++) {
                    const float* e = cb + k2 * C_;
                    float dot = 0.f;
#pragma unroll
                    for (int c = 0; c < C_; c++) dot = fmaf(xv[c], e[c], dot);
                    float d = fmaf(-2.f, dot, esq[k2]);
                    if (d < db) { db = d; kb = k2; }       // first index wins in-lane
                }
#pragma unroll
                for (int off = 8; off > 0; off >>= 1) {
                    float od = __shfl_xor_sync(gmask, db, off, 16);
                    int   ok = __shfl_xor_sync(gmask, kb, off, 16);
                    if (od < db || (od == db && ok < kb)) { db = od; kb = ok; }
                }
                if (l16 == 0) karr[r] = kb;
            }
        }
        __syncthreads();

        // ---- epilogue: out, loss, histogram, segment sums ----
        {
            int r = tid >> 1, half = tid & 1;
            int kk = karr[r];
            const float4* qp = (const float4*)(cb + kk * C_) + half * 8;
            float* op = out + (size_t)nb * CHW_ + hwb + r;
            float* sp = g_sums + kk * C_ + half * 32;
            int c0 = half * 32;
#pragma unroll
            for (int j = 0; j < 8; j++) {
                float4 q = qp[j];
                int c = c0 + 4 * j;
                float x0 = xf[c * 128 + r],       x1 = xf[(c + 1) * 128 + r];
                float x2 = xf[(c + 2) * 128 + r], x3 = xf[(c + 3) * 128 + r];
                op[(c + 0) * HW_] = x0 + (q.x - x0);
                op[(c + 1) * HW_] = x1 + (q.y - x1);
                op[(c + 2) * HW_] = x2 + (q.z - x2);
                op[(c + 3) * HW_] = x3 + (q.w - x3);
                float d0 = x0 - q.x, d1 = x1 - q.y, d2 = x2 - q.z, d3 = x3 - q.w;
                csum += d0 * d0 + d1 * d1 + d2 * d2 + d3 * d3;
                asm volatile("red.global.add.v4.f32 [%0], {%1,%2,%3,%4};"
                             :: "l"(sp + 4 * j), "f"(x0), "f"(x1), "f"(x2), "f"(x3)
                             : "memory");
            }
            if (tid < 128) atomicAdd(&scnt[karr[tid]], 1.f);
        }
        __syncthreads();
    }

    // ---- commit loss + histogram flush ----
#pragma unroll
    for (int off = 16; off > 0; off >>= 1)
        csum += __shfl_down_sync(0xffffffffu, csum, off);
    if (l == 0) sred[wid] = csum;
    __syncthreads();
    if (tid == 0) {
        float v = 0.f;
#pragma unroll
        for (int w = 0; w < 8; w++) v += sred[w];
        atomicAdd(&g_commit, v);
    }
#pragma unroll
    for (int r = 0; r < 2; r++) {
        int k = tid * 2 + r;
        float c = scnt[k];
        if (c != 0.f) atomicAdd(&g_counts[k], c);
    }
}

// ================= finalize (also re-zeros scratch for next replay) =================
__global__ void __launch_bounds__(512, 1) vq_finalize(
    const float* __restrict__ ema_cs, const float* __restrict__ ema_w,
    float* __restrict__ out)
{
    __shared__ float s_n[K_];
    __shared__ float s_u[K_];
    int k = threadIdx.x;
    float cnt = g_counts[k];
    g_counts[k] = 0.f;
    float ncs = 0.99f * ema_cs[k] + 0.01f * cnt;
    s_n[k] = ncs;
    s_u[k] = (cnt > 0.f) ? 1.f : 0.f;
    __syncthreads();
#pragma unroll
    for (int off = 256; off > 0; off >>= 1) {
        if (k < off) { s_n[k] += s_n[k + off]; s_u[k] += s_u[k + off]; }
        __syncthreads();
    }
    float n = s_n[0];
    float smoothed = (ncs + 1e-5f) / (n + K_ * 1e-5f) * n;
    float* cbo = out + OUT_ELEMS + 2;
#pragma unroll 4
    for (int c = 0; c < C_; c++) {
        int i = k * C_ + c;
        cbo[i] = (0.99f * ema_w[i] + 0.01f * g_sums[i]) / smoothed;
        g_sums[i] = 0.f;
    }
    if (k == 0) {
        out[OUT_ELEMS]     = g_commit * (1.0f / 8388608.0f);
        out[OUT_ELEMS + 1] = s_u[0];
        g_commit = 0.f;
    }
}

// ================= launch: [nop, main, finalize, nop] so ncu -s5 -c1 hits main =================
extern "C" void kernel_launch(void* const* d_in, const int* in_sizes, int n_in,
                              void* d_out, int out_size) {
    const float* x   = (const float*)d_in[0];
    const float* cb  = (const float*)d_in[1];
    const float* ecs = (const float*)d_in[2];
    const float* ew  = (const float*)d_in[3];
    float* out = (float*)d_out;

    cudaFuncSetAttribute(vq_main, cudaFuncAttributeMaxDynamicSharedMemorySize, SMEM_TOTAL);

    vq_nop<<<1, 32>>>();
    vq_main<<<GRID_, THREADS_, SMEM_TOTAL>>>(x, cb, out);
    vq_finalize<<<1, 512>>>(ecs, ew, out);
    vq_nop<<<1, 32>>>();
}

// round 15
// speedup vs baseline: 1.2564x; 1.2564x over previous
#include <cuda_runtime.h>
#include <cuda_fp16.h>

// VectorQuantizer B=32,C=64,H=64,W=64,K=512 — fp16 mma.sync screen + exact fp32 verify
// out layout: [0,8388608) ste-out | [+0] loss | [+1] unique | [+2,+32770) new_codebook

#define C_ 64
#define HW_ 4096
#define CHW_ 262144
#define K_ 512
#define NTILES 1024
#define GRID_ 148
#define THREADS_ 512
#define OUT_ELEMS 8388608

typedef unsigned int u32;

__device__ float g_counts[K_];
__device__ float g_sums[K_ * C_];
__device__ float g_commit;

// ---- smem layout (bytes) ----
#define OFF_BH   0        // codebook fp16 [512][64], 128B swizzled rows (64KB)
#define OFF_AH   65536    // x fp16 [128][64] swizzled (16KB)
#define OFF_SC   81920    // scores fp16 [128][512], 1KB rows swizzled (128KB)
#define OFF_NEGE 212992   // f32[512] = -0.5*|e|^2
#define OFF_ESQ  215040   // f32[512] = |e|^2
#define OFF_CNT  217088   // f32[512] histogram
#define OFF_B1S  219136   // f32[2][128] per-half row maxes
#define OFF_XN2  220160   // f32[128] = |x_r|^2
#define OFF_KARR 220672   // int[128] winners
#define OFF_RED  221184   // f32[16]
#define SMEM_TOTAL 221248

__device__ __forceinline__ int swz(int r, int c)  { return r * 128  + (c ^ ((r & 7) << 4)); }
__device__ __forceinline__ int swzs(int r, int c) { return r * 1024 + (c ^ ((r & 7) << 4)); }
__device__ __forceinline__ u32 h2u(__half2 h) { return *reinterpret_cast<u32*>(&h); }

#define MMA(c, a0, a1, a2, a3, b0, b1)                                        \
    asm volatile("mma.sync.aligned.m16n8k16.row.col.f32.f16.f16.f32 "         \
                 "{%0,%1,%2,%3}, {%4,%5,%6,%7}, {%8,%9}, {%0,%1,%2,%3};"      \
                 : "+f"((c)[0]), "+f"((c)[1]), "+f"((c)[2]), "+f"((c)[3])     \
                 : "r"(a0), "r"(a1), "r"(a2), "r"(a3), "r"(b0), "r"(b1))

// ================= main =================
__global__ void __launch_bounds__(THREADS_, 1) vq_main(
    const float* __restrict__ x, const float* __restrict__ cb,
    float* __restrict__ out)
{
    extern __shared__ char sm[];
    float* nege = (float*)(sm + OFF_NEGE);
    float* esq  = (float*)(sm + OFF_ESQ);
    float* scnt = (float*)(sm + OFF_CNT);
    float* b1s  = (float*)(sm + OFF_B1S);
    float* xn2  = (float*)(sm + OFF_XN2);
    int*   karr = (int*)(sm + OFF_KARR);
    float* sred = (float*)(sm + OFF_RED);

    const int tid = threadIdx.x;
    const int wid = tid >> 5, l = tid & 31;
    const int wRow = wid >> 1, wCol = wid & 1;   // 8x2 warp grid (16 rows x 256 codes)
    const int lq = l >> 2, lr = l & 3;

    // ---- prologue: codebook -> fp16 swizzled; |e|^2; Emax; zero hist ----
    const float4* cb4 = (const float4*)cb;
    for (int i = tid; i < K_ * 16; i += THREADS_) {
        float4 f = cb4[i];
        int code = i >> 4, j = i & 15;
        int a = swz(code, 8 * j);
        *(u32*)(sm + OFF_BH + a)     = h2u(__floats2half2_rn(f.x, f.y));
        *(u32*)(sm + OFF_BH + a + 4) = h2u(__floats2half2_rn(f.z, f.w));
    }
    {
        int k = tid;                              // 512 threads, one code each
        float s = 0.f;
#pragma unroll
        for (int j = 0; j < 16; j++) {
            float4 v = cb4[k * 16 + j];
            s += v.x * v.x + v.y * v.y + v.z * v.z + v.w * v.w;
        }
        esq[k] = s;
        nege[k] = -0.5f * s;
        scnt[k] = 0.f;
        float wm = s;
#pragma unroll
        for (int off = 16; off > 0; off >>= 1)
            wm = fmaxf(wm, __shfl_xor_sync(0xffffffffu, wm, off));
        if (l == 0) sred[wid] = wm;
    }
    __syncthreads();
    float emax2 = 0.f;
#pragma unroll
    for (int w = 0; w < 16; w++) emax2 = fmaxf(emax2, sred[w]);
    const float TAUC1 = sqrtf(emax2) * (1.0f / 256.0f);   // 2^-8 * max||e||
    __syncthreads();

    float csum = 0.f;

    for (int tile = blockIdx.x; tile < NTILES; tile += GRID_) {
        const int nb = tile >> 5;
        const int hwb = (tile & 31) * 128;
        const float* xb = x + (size_t)nb * CHW_ + hwb;

        if (tid < 128) xn2[tid] = 0.f;
        __syncthreads();

        // ---- load 128 x-rows -> fp16 swizzled + accumulate |x|^2 ----
        {
            const int r = tid & 127, cp0 = tid >> 7;
            float pn = 0.f;
#pragma unroll
            for (int it = 0; it < 8; it++) {
                int cp = it * 4 + cp0;
                float f0 = xb[(2 * cp) * HW_ + r];
                float f1 = xb[(2 * cp + 1) * HW_ + r];
                *(u32*)(sm + OFF_AH + swz(r, 4 * cp)) = h2u(__floats2half2_rn(f0, f1));
                pn += f0 * f0 + f1 * f1;
            }
            atomicAdd(&xn2[r], pn);
        }
        __syncthreads();

        // ---- A fragments (16 rows per warp) ----
        u32 Ah[4][4];
        {
            int r0 = wRow * 16 + lq, r1 = r0 + 8;
#pragma unroll
            for (int ks = 0; ks < 4; ks++) {
                int cb0 = 32 * ks + 4 * lr;
                Ah[ks][0] = *(u32*)(sm + OFF_AH + swz(r0, cb0));
                Ah[ks][1] = *(u32*)(sm + OFF_AH + swz(r1, cb0));
                Ah[ks][2] = *(u32*)(sm + OFF_AH + swz(r0, cb0 + 16));
                Ah[ks][3] = *(u32*)(sm + OFF_AH + swz(r1, cb0 + 16));
            }
        }

        // ---- pass1: 32 chunks x 8 codes; 4 MMAs each; store scores + track max ----
        float b1v0 = -3.402823466e38f, b1v1 = -3.402823466e38f;
        const int r0 = wRow * 16 + lq;
#pragma unroll 1
        for (int ch = 0; ch < 32; ch++) {
            int colb = wCol * 256 + ch * 8;
            int n = colb + lq;
            float C[4] = {0.f, 0.f, 0.f, 0.f};
#pragma unroll
            for (int ks = 0; ks < 4; ks++) {
                int cbB = 32 * ks + 4 * lr;
                u32 b0 = *(u32*)(sm + OFF_BH + swz(n, cbB));
                u32 b1 = *(u32*)(sm + OFF_BH + swz(n, cbB + 16));
                MMA(C, Ah[ks][0], Ah[ks][1], Ah[ks][2], Ah[ks][3], b0, b1);
            }
            int col0 = colb + 2 * lr;
            float ng0 = nege[col0], ng1 = nege[col0 + 1];
            float s0 = C[0] + ng0, s1 = C[1] + ng1;
            float s2 = C[2] + ng0, s3 = C[3] + ng1;
            *(u32*)(sm + OFF_SC + swzs(r0,     2 * col0)) = h2u(__floats2half2_rn(s0, s1));
            *(u32*)(sm + OFF_SC + swzs(r0 + 8, 2 * col0)) = h2u(__floats2half2_rn(s2, s3));
            b1v0 = fmaxf(b1v0, fmaxf(s0, s1));
            b1v1 = fmaxf(b1v1, fmaxf(s2, s3));
        }
#pragma unroll
        for (int off = 1; off <= 2; off <<= 1) {
            b1v0 = fmaxf(b1v0, __shfl_xor_sync(0xffffffffu, b1v0, off));
            b1v1 = fmaxf(b1v1, __shfl_xor_sync(0xffffffffu, b1v1, off));
        }
        if (lr == 0) {
            b1s[wCol * 128 + r0]     = b1v0;
            b1s[wCol * 128 + r0 + 8] = b1v1;
        }
        __syncthreads();

        // ---- pass2: candidate scan + exact fp32 verify.
        // All shfls are executed UNCONDITIONALLY by every lane of warps 0-7
        // (the R14 hang was a shfl inside pair-divergent control flow).
        if (tid < 256) {
            const int r = tid >> 1, half = tid & 1;
            float m = fmaxf(b1s[r], b1s[128 + r]);
            float thr = m - (TAUC1 * sqrtf(xn2[r]) + 0.05f);
            int cand0 = 0;
            int cnt = 0;
#pragma unroll 4
            for (int j = 0; j < 128; j++) {
                u32 v = *(u32*)(sm + OFF_SC + swzs(r, (half * 512 + 4 * j)));
                float2 g = __half22float2(*reinterpret_cast<__half2*>(&v));
                int c0 = half * 256 + 2 * j;
                if (g.x >= thr) { if (cnt == 0) cand0 = c0;     cnt++; }
                if (g.y >= thr) { if (cnt == 0) cand0 = c0 + 1; cnt++; }
            }
            int pcnt = __shfl_xor_sync(0xffffffffu, cnt, 1);
            int pc0  = __shfl_xor_sync(0xffffffffu, cand0, 1);
            bool needv = (cnt + pcnt != 1);
            float db = 3.402823466e38f;
            int kb = 0x7FFFFFFF;
            if (needv && cnt > 0) {
                const float* xr = x + (size_t)nb * CHW_ + hwb + r;
                for (int j = 0; j < 128; j++) {
                    u32 v = *(u32*)(sm + OFF_SC + swzs(r, (half * 512 + 4 * j)));
                    float2 g = __half22float2(*reinterpret_cast<__half2*>(&v));
                    int c0 = half * 256 + 2 * j;
#pragma unroll
                    for (int e2 = 0; e2 < 2; e2++) {
                        float sv = e2 ? g.y : g.x;
                        if (sv >= thr) {
                            int k = c0 + e2;
                            const float* e = cb + k * C_;
                            float dot = 0.f;
#pragma unroll
                            for (int c = 0; c < C_; c++) dot = fmaf(xr[c * HW_], e[c], dot);
                            float d = fmaf(-2.f, dot, esq[k]);
                            if (d < db) { db = d; kb = k; }   // ascending k: first wins
                        }
                    }
                }
            }
            // unconditional pair-merge (all 32 lanes of each warp execute)
            float pd = __shfl_xor_sync(0xffffffffu, db, 1);
            int   pk = __shfl_xor_sync(0xffffffffu, kb, 1);
            if (pd < db || (pd == db && pk < kb)) { db = pd; kb = pk; }
            int kk = needv ? kb : (cnt == 1 ? cand0 : pc0);
            if (half == 0) karr[r] = kk;
        }
        __syncthreads();

        // ---- epilogue: out, loss, histogram, segment sums ----
        {
            const int r = tid >> 2, q = tid & 3;
            const int kk = karr[r];
            const float* xr = x + (size_t)nb * CHW_ + hwb + r;
            float* op = out + (size_t)nb * CHW_ + hwb + r;
            const float4* qp = (const float4*)(cb + kk * C_) + q * 4;
            float* sp = g_sums + kk * C_ + q * 16;
#pragma unroll
            for (int j = 0; j < 4; j++) {
                float4 e = qp[j];
                int c = q * 16 + 4 * j;
                float x0 = xr[c * HW_],       x1 = xr[(c + 1) * HW_];
                float x2 = xr[(c + 2) * HW_], x3 = xr[(c + 3) * HW_];
                op[(c + 0) * HW_] = x0 + (e.x - x0);
                op[(c + 1) * HW_] = x1 + (e.y - x1);
                op[(c + 2) * HW_] = x2 + (e.z - x2);
                op[(c + 3) * HW_] = x3 + (e.w - x3);
                float d0 = x0 - e.x, d1 = x1 - e.y, d2 = x2 - e.z, d3 = x3 - e.w;
                csum += d0 * d0 + d1 * d1 + d2 * d2 + d3 * d3;
                asm volatile("red.global.add.v4.f32 [%0], {%1,%2,%3,%4};"
                             :: "l"(sp + 4 * j), "f"(x0), "f"(x1), "f"(x2), "f"(x3)
                             : "memory");
            }
            if (tid < 128) atomicAdd(&scnt[karr[tid]], 1.f);
        }
        __syncthreads();
    }

    // ---- commit loss reduce + histogram flush ----
#pragma unroll
    for (int off = 16; off > 0; off >>= 1)
        csum += __shfl_down_sync(0xffffffffu, csum, off);
    if (l == 0) sred[wid] = csum;
    __syncthreads();
    if (tid == 0) {
        float v = 0.f;
#pragma unroll
        for (int w = 0; w < 16; w++) v += sred[w];
        atomicAdd(&g_commit, v);
    }
    {
        float c = scnt[tid];
        if (c != 0.f) atomicAdd(&g_counts[tid], c);
    }
}

// ================= finalize (re-zeros scratch for next replay) =================
__global__ void __launch_bounds__(512, 1) vq_finalize(
    const float* __restrict__ ema_cs, const float* __restrict__ ema_w,
    float* __restrict__ out)
{
    __shared__ float s_n[K_];
    __shared__ float s_u[K_];
    int k = threadIdx.x;
    float cnt = g_counts[k];
    g_counts[k] = 0.f;
    float ncs = 0.99f * ema_cs[k] + 0.01f * cnt;
    s_n[k] = ncs;
    s_u[k] = (cnt > 0.f) ? 1.f : 0.f;
    __syncthreads();
#pragma unroll
    for (int off = 256; off > 0; off >>= 1) {
        if (k < off) { s_n[k] += s_n[k + off]; s_u[k] += s_u[k + off]; }
        __syncthreads();
    }
    float n = s_n[0];
    float smoothed = (ncs + 1e-5f) / (n + K_ * 1e-5f) * n;
    float* cbo = out + OUT_ELEMS + 2;
#pragma unroll 4
    for (int c = 0; c < C_; c++) {
        int i = k * C_ + c;
        cbo[i] = (0.99f * ema_w[i] + 0.01f * g_sums[i]) / smoothed;
        g_sums[i] = 0.f;
    }
    if (k == 0) {
        out[OUT_ELEMS]     = g_commit * (1.0f / 8388608.0f);
        out[OUT_ELEMS + 1] = s_u[0];
        g_commit = 0.f;
    }
}

// ================= launch: main FIRST so graph-mode ncu (-c 1) profiles it =================
extern "C" void kernel_launch(void* const* d_in, const int* in_sizes, int n_in,
                              void* d_out, int out_size) {
    const float* x   = (const float*)d_in[0];
    const float* cb  = (const float*)d_in[1];
    const float* ecs = (const float*)d_in[2];
    const float* ew  = (const float*)d_in[3];
    float* out = (float*)d_out;

    cudaFuncSetAttribute(vq_main, cudaFuncAttributeMaxDynamicSharedMemorySize, SMEM_TOTAL);

    vq_main<<<GRID_, THREADS_, SMEM_TOTAL>>>(x, cb, out);
    vq_finalize<<<1, 512>>>(ecs, ew, out);
}

// round 17
// speedup vs baseline: 1.8056x; 1.4371x over previous
#include <cuda_runtime.h>
#include <cuda_fp16.h>

// VectorQuantizer B=32,C=64,H=64,W=64,K=512 — fp16 mma.sync screen + exact fp32 verify
// out layout: [0,8388608) ste-out | [+0] loss | [+1] unique | [+2,+32770) new_codebook

#define C_ 64
#define HW_ 4096
#define CHW_ 262144
#define K_ 512
#define NTILES 1024
#define GRID_ 148
#define THREADS_ 512
#define OUT_ELEMS 8388608

typedef unsigned int u32;

__device__ float g_counts[K_];
__device__ float g_sums[K_ * C_];
__device__ float g_commit;

// ---- smem layout (bytes) ----
#define OFF_BH   0        // codebook fp16 [512][64], 128B swizzled rows (64KB)
#define OFF_AH   65536    // x fp16 [128][64] swizzled (16KB)
#define OFF_SC   81920    // scores fp16 [128][512], 1KB rows swizzled (128KB)
#define OFF_NEGE 212992   // f32[512] = -0.5*|e|^2
#define OFF_ESQ  215040   // f32[512] = |e|^2
#define OFF_CNT  217088   // f32[512] histogram
#define OFF_B1S  219136   // f32[2][128] per-half row maxes
#define OFF_XN2  220160   // f32[128] = |x_r|^2
#define OFF_KARR 220672   // int[128] winners
#define OFF_RED  221184   // f32[16]
#define SMEM_TOTAL 221248

__device__ __forceinline__ int swz(int r, int c)  { return r * 128  + (c ^ ((r & 7) << 4)); }
__device__ __forceinline__ int swzs(int r, int c) { return r * 1024 + (c ^ ((r & 7) << 4)); }
__device__ __forceinline__ u32 h2u(__half2 h) { return *reinterpret_cast<u32*>(&h); }

#define MMA(c, a0, a1, a2, a3, b0, b1)                                        \
    asm volatile("mma.sync.aligned.m16n8k16.row.col.f32.f16.f16.f32 "         \
                 "{%0,%1,%2,%3}, {%4,%5,%6,%7}, {%8,%9}, {%0,%1,%2,%3};"      \
                 : "+f"((c)[0]), "+f"((c)[1]), "+f"((c)[2]), "+f"((c)[3])     \
                 : "r"(a0), "r"(a1), "r"(a2), "r"(a3), "r"(b0), "r"(b1))

__global__ void vq_nop() {}

// ================= main =================
__global__ void __launch_bounds__(THREADS_, 1) vq_main(
    const float* __restrict__ x, const float* __restrict__ cb,
    float* __restrict__ out)
{
    extern __shared__ char sm[];
    float* nege = (float*)(sm + OFF_NEGE);
    float* esq  = (float*)(sm + OFF_ESQ);
    float* scnt = (float*)(sm + OFF_CNT);
    float* b1s  = (float*)(sm + OFF_B1S);
    float* xn2  = (float*)(sm + OFF_XN2);
    int*   karr = (int*)(sm + OFF_KARR);
    float* sred = (float*)(sm + OFF_RED);

    const int tid = threadIdx.x;
    const int wid = tid >> 5, l = tid & 31;
    const int wRow = wid >> 1, wCol = wid & 1;   // 8x2 warp grid (16 rows x 256 codes)
    const int lq = l >> 2, lr = l & 3;

    // ---- prologue: codebook -> fp16 swizzled; |e|^2; Emax; zero hist ----
    const float4* cb4 = (const float4*)cb;
    for (int i = tid; i < K_ * 16; i += THREADS_) {
        float4 f = cb4[i];
        int code = i >> 4, j = i & 15;
        int a = swz(code, 8 * j);
        *(u32*)(sm + OFF_BH + a)     = h2u(__floats2half2_rn(f.x, f.y));
        *(u32*)(sm + OFF_BH + a + 4) = h2u(__floats2half2_rn(f.z, f.w));
    }
    {
        int k = tid;                              // 512 threads, one code each
        float s = 0.f;
#pragma unroll
        for (int j = 0; j < 16; j++) {
            float4 v = cb4[k * 16 + j];
            s += v.x * v.x + v.y * v.y + v.z * v.z + v.w * v.w;
        }
        esq[k] = s;
        nege[k] = -0.5f * s;
        scnt[k] = 0.f;
        float wm = s;
#pragma unroll
        for (int off = 16; off > 0; off >>= 1)
            wm = fmaxf(wm, __shfl_xor_sync(0xffffffffu, wm, off));
        if (l == 0) sred[wid] = wm;
    }
    __syncthreads();
    float emax2 = 0.f;
#pragma unroll
    for (int w = 0; w < 16; w++) emax2 = fmaxf(emax2, sred[w]);
    // Rigorous fp16-mma bound: 2*eps = ||x||*Emax*2^-9 -> Emax/512; /480 adds 6% cushion.
    const float TAUC1 = sqrtf(emax2) * (1.0f / 480.0f);
    __syncthreads();

    float csum = 0.f;

    for (int tile = blockIdx.x; tile < NTILES; tile += GRID_) {
        const int nb = tile >> 5;
        const int hwb = (tile & 31) * 128;
        const float* xb = x + (size_t)nb * CHW_ + hwb;

        if (tid < 128) xn2[tid] = 0.f;
        __syncthreads();

        // ---- load 128 x-rows -> fp16 swizzled + accumulate |x|^2 ----
        {
            const int r = tid & 127, cp0 = tid >> 7;
            float pn = 0.f;
#pragma unroll
            for (int it = 0; it < 8; it++) {
                int cp = it * 4 + cp0;
                float f0 = xb[(2 * cp) * HW_ + r];
                float f1 = xb[(2 * cp + 1) * HW_ + r];
                *(u32*)(sm + OFF_AH + swz(r, 4 * cp)) = h2u(__floats2half2_rn(f0, f1));
                pn += f0 * f0 + f1 * f1;
            }
            atomicAdd(&xn2[r], pn);
        }
        __syncthreads();

        // ---- A fragments (16 rows per warp) ----
        u32 Ah[4][4];
        {
            int r0 = wRow * 16 + lq, r1 = r0 + 8;
#pragma unroll
            for (int ks = 0; ks < 4; ks++) {
                int cb0 = 32 * ks + 4 * lr;
                Ah[ks][0] = *(u32*)(sm + OFF_AH + swz(r0, cb0));
                Ah[ks][1] = *(u32*)(sm + OFF_AH + swz(r1, cb0));
                Ah[ks][2] = *(u32*)(sm + OFF_AH + swz(r0, cb0 + 16));
                Ah[ks][3] = *(u32*)(sm + OFF_AH + swz(r1, cb0 + 16));
            }
        }

        // ---- pass1: 32 chunks x 8 codes; 4 MMAs each; store scores + track max ----
        float b1v0 = -3.402823466e38f, b1v1 = -3.402823466e38f;
        const int r0 = wRow * 16 + lq;
#pragma unroll 1
        for (int ch = 0; ch < 32; ch++) {
            int colb = wCol * 256 + ch * 8;
            int n = colb + lq;
            float C[4] = {0.f, 0.f, 0.f, 0.f};
#pragma unroll
            for (int ks = 0; ks < 4; ks++) {
                int cbB = 32 * ks + 4 * lr;
                u32 b0 = *(u32*)(sm + OFF_BH + swz(n, cbB));
                u32 b1 = *(u32*)(sm + OFF_BH + swz(n, cbB + 16));
                MMA(C, Ah[ks][0], Ah[ks][1], Ah[ks][2], Ah[ks][3], b0, b1);
            }
            int col0 = colb + 2 * lr;
            float ng0 = nege[col0], ng1 = nege[col0 + 1];
            float s0 = C[0] + ng0, s1 = C[1] + ng1;
            float s2 = C[2] + ng0, s3 = C[3] + ng1;
            *(u32*)(sm + OFF_SC + swzs(r0,     2 * col0)) = h2u(__floats2half2_rn(s0, s1));
            *(u32*)(sm + OFF_SC + swzs(r0 + 8, 2 * col0)) = h2u(__floats2half2_rn(s2, s3));
            b1v0 = fmaxf(b1v0, fmaxf(s0, s1));
            b1v1 = fmaxf(b1v1, fmaxf(s2, s3));
        }
#pragma unroll
        for (int off = 1; off <= 2; off <<= 1) {
            b1v0 = fmaxf(b1v0, __shfl_xor_sync(0xffffffffu, b1v0, off));
            b1v1 = fmaxf(b1v1, __shfl_xor_sync(0xffffffffu, b1v1, off));
        }
        if (lr == 0) {
            b1s[wCol * 128 + r0]     = b1v0;
            b1s[wCol * 128 + r0 + 8] = b1v1;
        }
        __syncthreads();

        // ---- pass2: candidate scan + exact fp32 verify.
        // All shfls executed UNCONDITIONALLY by every lane of warps 0-7.
        if (tid < 256) {
            const int r = tid >> 1, half = tid & 1;
            float m = fmaxf(b1s[r], b1s[128 + r]);
            float thr = m - (TAUC1 * sqrtf(xn2[r]) + 0.035f);
            int cand0 = 0;
            int cnt = 0;
#pragma unroll 4
            for (int j = 0; j < 128; j++) {
                u32 v = *(u32*)(sm + OFF_SC + swzs(r, (half * 512 + 4 * j)));
                float2 g = __half22float2(*reinterpret_cast<__half2*>(&v));
                int c0 = half * 256 + 2 * j;
                if (g.x >= thr) { if (cnt == 0) cand0 = c0;     cnt++; }
                if (g.y >= thr) { if (cnt == 0) cand0 = c0 + 1; cnt++; }
            }
            int pcnt = __shfl_xor_sync(0xffffffffu, cnt, 1);
            int pc0  = __shfl_xor_sync(0xffffffffu, cand0, 1);
            bool needv = (cnt + pcnt != 1);
            float db = 3.402823466e38f;
            int kb = 0x7FFFFFFF;
            if (needv && cnt > 0) {
                const float* xr = x + (size_t)nb * CHW_ + hwb + r;
                for (int j = 0; j < 128; j++) {
                    u32 v = *(u32*)(sm + OFF_SC + swzs(r, (half * 512 + 4 * j)));
                    float2 g = __half22float2(*reinterpret_cast<__half2*>(&v));
                    int c0 = half * 256 + 2 * j;
#pragma unroll
                    for (int e2 = 0; e2 < 2; e2++) {
                        float sv = e2 ? g.y : g.x;
                        if (sv >= thr) {
                            int k = c0 + e2;
                            const float* e = cb + k * C_;
                            float dot = 0.f;
#pragma unroll
                            for (int c = 0; c < C_; c++) dot = fmaf(xr[c * HW_], e[c], dot);
                            float d = fmaf(-2.f, dot, esq[k]);
                            if (d < db) { db = d; kb = k; }   // ascending k: first wins
                        }
                    }
                }
            }
            // unconditional pair-merge (all 32 lanes of each warp execute)
            float pd = __shfl_xor_sync(0xffffffffu, db, 1);
            int   pk = __shfl_xor_sync(0xffffffffu, kb, 1);
            if (pd < db || (pd == db && pk < kb)) { db = pd; kb = pk; }
            int kk = needv ? kb : (cnt == 1 ? cand0 : pc0);
            if (half == 0) karr[r] = kk;
        }
        __syncthreads();

        // ---- epilogue: out, loss, histogram, segment sums ----
        {
            const int r = tid >> 2, q = tid & 3;
            const int kk = karr[r];
            const float* xr = x + (size_t)nb * CHW_ + hwb + r;
            float* op = out + (size_t)nb * CHW_ + hwb + r;
            const float4* qp = (const float4*)(cb + kk * C_) + q * 4;
            float* sp = g_sums + kk * C_ + q * 16;
#pragma unroll
            for (int j = 0; j < 4; j++) {
                float4 e = qp[j];
                int c = q * 16 + 4 * j;
                float x0 = xr[c * HW_],       x1 = xr[(c + 1) * HW_];
                float x2 = xr[(c + 2) * HW_], x3 = xr[(c + 3) * HW_];
                op[(c + 0) * HW_] = x0 + (e.x - x0);
                op[(c + 1) * HW_] = x1 + (e.y - x1);
                op[(c + 2) * HW_] = x2 + (e.z - x2);
                op[(c + 3) * HW_] = x3 + (e.w - x3);
                float d0 = x0 - e.x, d1 = x1 - e.y, d2 = x2 - e.z, d3 = x3 - e.w;
                csum += d0 * d0 + d1 * d1 + d2 * d2 + d3 * d3;
                asm volatile("red.global.add.v4.f32 [%0], {%1,%2,%3,%4};"
                             :: "l"(sp + 4 * j), "f"(x0), "f"(x1), "f"(x2), "f"(x3)
                             : "memory");
            }
            if (tid < 128) atomicAdd(&scnt[karr[tid]], 1.f);
        }
        __syncthreads();
    }

    // ---- commit loss reduce + histogram flush ----
#pragma unroll
    for (int off = 16; off > 0; off >>= 1)
        csum += __shfl_down_sync(0xffffffffu, csum, off);
    if (l == 0) sred[wid] = csum;
    __syncthreads();
    if (tid == 0) {
        float v = 0.f;
#pragma unroll
        for (int w = 0; w < 16; w++) v += sred[w];
        atomicAdd(&g_commit, v);
    }
    {
        float c = scnt[tid];
        if (c != 0.f) atomicAdd(&g_counts[tid], c);
    }
}

// ====== finA: parallel EMA update (128 blocks x 256 thr; block b -> codebook rows 4b..4b+3) ======
__global__ void __launch_bounds__(256, 1) vq_finA(
    const float* __restrict__ ema_cs, const float* __restrict__ ema_w,
    float* __restrict__ out)
{
    __shared__ float s_n[8];
    __shared__ float s_u[8];
    __shared__ float s_tot[2];
    const int t = threadIdx.x, b = blockIdx.x;
    const int wd = t >> 5, ln = t & 31;

    // redundant per-block reduction of n = sum(new_cluster_size), u = sum(counts>0)
    float nloc = 0.f, uloc = 0.f;
#pragma unroll
    for (int rr = 0; rr < 2; rr++) {
        int k = t + rr * 256;
        float cnt = g_counts[k];
        nloc += 0.99f * ema_cs[k] + 0.01f * cnt;
        uloc += (cnt > 0.f) ? 1.f : 0.f;
    }
#pragma unroll
    for (int off = 16; off > 0; off >>= 1) {
        nloc += __shfl_down_sync(0xffffffffu, nloc, off);
        uloc += __shfl_down_sync(0xffffffffu, uloc, off);
    }
    if (ln == 0) { s_n[wd] = nloc; s_u[wd] = uloc; }
    __syncthreads();
    if (t == 0) {
        float n = 0.f, u = 0.f;
#pragma unroll
        for (int w = 0; w < 8; w++) { n += s_n[w]; u += s_u[w]; }
        s_tot[0] = n; s_tot[1] = u;
    }
    __syncthreads();
    const float n = s_tot[0];

    // write this block's 4 codebook rows
    const int row = b * 4 + (t >> 6), c = t & 63;
    const float ncs = 0.99f * ema_cs[row] + 0.01f * g_counts[row];
    const float smoothed = (ncs + 1e-5f) / (n + K_ * 1e-5f) * n;
    const int i = row * C_ + c;
    out[OUT_ELEMS + 2 + i] = (0.99f * ema_w[i] + 0.01f * g_sums[i]) / smoothed;

    if (b == 0 && t == 0) {
        out[OUT_ELEMS]     = g_commit * (1.0f / 8388608.0f);
        out[OUT_ELEMS + 1] = s_tot[1];
    }
}

// ====== finB: zero scratch for next replay (64 blocks x 512 thr) ======
__global__ void __launch_bounds__(512, 1) vq_finB() {
    const int t = threadIdx.x, b = blockIdx.x;
    g_sums[b * 512 + t] = 0.f;
    if (b == 0) g_counts[t] = 0.f;
    if (b == 0 && t == 0) g_commit = 0.f;
}

// ====== launch: [main, finA, finB, nop, nop] (L=5 -> 6th launch = main for ncu) ======
extern "C" void kernel_launch(void* const* d_in, const int* in_sizes, int n_in,
                              void* d_out, int out_size) {
    const float* x   = (const float*)d_in[0];
    const float* cb  = (const float*)d_in[1];
    const float* ecs = (const float*)d_in[2];
    const float* ew  = (const float*)d_in[3];
    float* out = (float*)d_out;

    cudaFuncSetAttribute(vq_main, cudaFuncAttributeMaxDynamicSharedMemorySize, SMEM_TOTAL);

    vq_main<<<GRID_, THREADS_, SMEM_TOTAL>>>(x, cb, out);
    vq_finA<<<128, 256>>>(ecs, ew, out);
    vq_finB<<<64, 512>>>();
    vq_nop<<<1, 32>>>();
    vq_nop<<<1, 32>>>();
}